// round 2
// baseline (speedup 1.0000x reference)
#include <cuda_runtime.h>
#include <math.h>

#define FULL 0xFFFFFFFFu

constexpr int B  = 64;
constexpr int P  = 4096;
constexpr int W  = 16;
constexpr int D  = 128;
constexpr int Dw = 64;

// W1r is (D, D+4) row-major -> row stride 132
// W1t is (D, 2*Dw+2) row-major -> row stride 130

// Scratch (device globals; no allocation allowed)
__device__ float g_WT[D * D];     // transposed W1r_e: g_WT[k*D + d] = W1r[d,k]
__device__ float g_bias[D];       // b1r[d] + 0.95 * W1r[d,130]
__device__ float g_src[W * D];    // (wh_emb @ W1t_src.T)[s,d] + b1t[d]
__device__ float g_tgt[W * D];    // (wh_emb @ W1t_tgt.T)[t,d]
__device__ float g_emb[P * D];    // emb_term(+bias+0.95 fold) per part

// ---------------------------------------------------------------------------
// k_pre: transpose W1r_e, build bias, build src/tgt pair terms (tiny)
// grid: 25 blocks x 256 threads
// ---------------------------------------------------------------------------
__global__ void k_pre(const float* __restrict__ wh_emb,
                      const float* __restrict__ W1r,
                      const float* __restrict__ b1r,
                      const float* __restrict__ W1t,
                      const float* __restrict__ b1t) {
    int blk = blockIdx.x, tid = threadIdx.x;
    if (blk < 8) {
        // transpose 128x128 region of W1r
        #pragma unroll
        for (int j = 0; j < 8; j++) {
            int e = blk * 2048 + tid + j * 256;
            int d = e >> 7, k = e & 127;
            g_WT[k * D + d] = W1r[d * 132 + k];
        }
    } else if (blk < 24) {
        // src/tgt tiny GEMMs: 2 * 16 * 128 outputs, one per thread
        int out = (blk - 8) * 256 + tid;       // 0..4095
        int arr = out >> 11;                   // 0 = src, 1 = tgt
        int rem = out & 2047;
        int s = rem >> 7, d = rem & 127;
        const float* wrow = wh_emb + s * Dw;
        const float* wcol = W1t + d * 130 + arr * Dw;
        float acc = (arr == 0) ? b1t[d] : 0.f;
        #pragma unroll 8
        for (int k = 0; k < Dw; k++) acc = fmaf(wrow[k], wcol[k], acc);
        if (arr == 0) g_src[s * D + d] = acc;
        else          g_tgt[s * D + d] = acc;
    } else {
        if (tid < D) g_bias[tid] = b1r[tid] + 0.95f * W1r[tid * 132 + 130];
    }
}

// ---------------------------------------------------------------------------
// k_emb: g_emb[p,d] = sum_k part_emb[p,k] * W1r[d,k]  (+ bias fold)
// warp per p, lanes over d (4 each). grid: 512 x 256
// ---------------------------------------------------------------------------
__global__ void k_emb(const float* __restrict__ part_emb) {
    int w = threadIdx.x >> 5, lane = threadIdx.x & 31;
    int p = blockIdx.x * 8 + w;
    const float4* erow = (const float4*)(part_emb + p * D);
    float4 acc = ((const float4*)g_bias)[lane];
    #pragma unroll 4
    for (int k4 = 0; k4 < 32; k4++) {
        float4 e = __ldg(&erow[k4]);
        const float4* wt = (const float4*)(g_WT + k4 * 4 * D);
        float4 w0 = wt[lane];
        float4 w1 = wt[32 + lane];
        float4 w2 = wt[64 + lane];
        float4 w3 = wt[96 + lane];
        acc.x = fmaf(e.x, w0.x, fmaf(e.y, w1.x, fmaf(e.z, w2.x, fmaf(e.w, w3.x, acc.x))));
        acc.y = fmaf(e.x, w0.y, fmaf(e.y, w1.y, fmaf(e.z, w2.y, fmaf(e.w, w3.y, acc.y))));
        acc.z = fmaf(e.x, w0.z, fmaf(e.y, w1.z, fmaf(e.z, w2.z, fmaf(e.w, w3.z, acc.z))));
        acc.w = fmaf(e.x, w0.w, fmaf(e.y, w1.w, fmaf(e.z, w2.w, fmaf(e.w, w3.w, acc.w))));
    }
    ((float4*)(g_emb + p * D))[lane] = acc;
}

// ---------------------------------------------------------------------------
// k_reorder: per (b,p): softplus(W2r . relu(emb + df*c0 + lt*c1 + cs*c3))
// warp per item (grid-stride). grid: 2048 x 256
// ---------------------------------------------------------------------------
__global__ void k_reorder(const float* __restrict__ cur_stock,
                          const float* __restrict__ demand,
                          const float* __restrict__ lead,
                          const float* __restrict__ W1r,
                          const float* __restrict__ W2r,
                          const float* __restrict__ b2r,
                          float* __restrict__ out) {
    __shared__ float sC[4 * 128];  // c0, c1, c3, v
    int tid = threadIdx.x;
    if (tid < 128) {
        sC[tid]       = W1r[tid * 132 + 128];
        sC[128 + tid] = W1r[tid * 132 + 129];
        sC[256 + tid] = W1r[tid * 132 + 131];
        sC[384 + tid] = W2r[tid];
    }
    __syncthreads();
    int w = tid >> 5, lane = tid & 31;
    float4 c0 = ((float4*)sC)[lane];
    float4 c1 = ((float4*)(sC + 128))[lane];
    float4 c3 = ((float4*)(sC + 256))[lane];
    float4 v  = ((float4*)(sC + 384))[lane];
    float bb = b2r[0];
    for (int item = blockIdx.x * 8 + w; item < B * P; item += gridDim.x * 8) {
        int p = item & (P - 1);
        float df = demand[item], lt = lead[item], cs = cur_stock[item];
        float4 e = ((const float4*)(g_emb + p * D))[lane];
        float4 h;
        h.x = fmaxf(fmaf(cs, c3.x, fmaf(lt, c1.x, fmaf(df, c0.x, e.x))), 0.f);
        h.y = fmaxf(fmaf(cs, c3.y, fmaf(lt, c1.y, fmaf(df, c0.y, e.y))), 0.f);
        h.z = fmaxf(fmaf(cs, c3.z, fmaf(lt, c1.z, fmaf(df, c0.z, e.z))), 0.f);
        h.w = fmaxf(fmaf(cs, c3.w, fmaf(lt, c1.w, fmaf(df, c0.w, e.w))), 0.f);
        float s = fmaf(h.x, v.x, fmaf(h.y, v.y, fmaf(h.z, v.z, h.w * v.w)));
        s += __shfl_xor_sync(FULL, s, 16);
        s += __shfl_xor_sync(FULL, s, 8);
        s += __shfl_xor_sync(FULL, s, 4);
        s += __shfl_xor_sync(FULL, s, 2);
        s += __shfl_xor_sync(FULL, s, 1);
        if (lane == 0) {
            float x = s + bb;
            // stable softplus = max(x,0) + log1p(exp(-|x|))
            out[item] = fmaxf(x, 0.f) + log1pf(expf(-fabsf(x)));
        }
    }
}

// ---------------------------------------------------------------------------
// k_transfer: warp per p; ballot-compacted (s,t) pair iteration.
// grid: 256 x 512 (16 warps -> 16 p per block)
// ---------------------------------------------------------------------------
__global__ void k_transfer(const float* __restrict__ wstk,
                           const float* __restrict__ wdem,
                           const float* __restrict__ W1t,
                           const float* __restrict__ W2t,
                           const float* __restrict__ b2t,
                           float* __restrict__ outT) {
    __shared__ float sSrc[W * D];
    __shared__ float sTgt[W * D];
    __shared__ float sWs[D], sWd[D], sV[D];
    __shared__ float sRes[256 * 17];   // [s*16+t][warp] padded
    int tid = threadIdx.x;
    for (int i = tid; i < W * D; i += 512) { sSrc[i] = g_src[i]; sTgt[i] = g_tgt[i]; }
    if (tid < D) {
        sWs[tid] = W1t[tid * 130 + 128];
        sWd[tid] = W1t[tid * 130 + 129];
        sV[tid]  = W2t[tid];
    }
    __syncthreads();

    int w = tid >> 5, lane = tid & 31;
    int p = blockIdx.x * 16 + w;
    float4 ws4 = ((float4*)sWs)[lane];
    float4 wd4 = ((float4*)sWd)[lane];
    float4 v4  = ((float4*)sV)[lane];

    float sv = 0.f;
    if (lane < W) sv = wstk[lane * P + p] - wdem[lane * P + p];
    unsigned pos = __ballot_sync(FULL, (lane < W) && (sv > 0.f));
    unsigned neg = __ballot_sync(FULL, (lane < W) && (sv < 0.f));

    for (int i = lane; i < 256; i += 32) sRes[i * 17 + w] = 0.f;

    float b2 = b2t[0];
    for (unsigned pm = pos; pm; pm &= pm - 1) {
        int s = __ffs(pm) - 1;
        float ssp = __shfl_sync(FULL, sv, s);
        float4 sr = ((float4*)(sSrc + s * D))[lane];
        float4 base;
        base.x = fmaf(ssp, ws4.x, sr.x);
        base.y = fmaf(ssp, ws4.y, sr.y);
        base.z = fmaf(ssp, ws4.z, sr.z);
        base.w = fmaf(ssp, ws4.w, sr.w);
        for (unsigned nm = neg; nm; nm &= nm - 1) {
            int t = __ffs(nm) - 1;
            float dn = -__shfl_sync(FULL, sv, t);
            float4 tg = ((float4*)(sTgt + t * D))[lane];
            float4 h;
            h.x = fmaxf(base.x + fmaf(dn, wd4.x, tg.x), 0.f);
            h.y = fmaxf(base.y + fmaf(dn, wd4.y, tg.y), 0.f);
            h.z = fmaxf(base.z + fmaf(dn, wd4.z, tg.z), 0.f);
            h.w = fmaxf(base.w + fmaf(dn, wd4.w, tg.w), 0.f);
            float sc = fmaf(h.x, v4.x, fmaf(h.y, v4.y, fmaf(h.z, v4.z, h.w * v4.w)));
            sc += __shfl_xor_sync(FULL, sc, 16);
            sc += __shfl_xor_sync(FULL, sc, 8);
            sc += __shfl_xor_sync(FULL, sc, 4);
            sc += __shfl_xor_sync(FULL, sc, 2);
            sc += __shfl_xor_sync(FULL, sc, 1);
            if (lane == 0) {
                float x = sc + b2;
                float sig = 1.f / (1.f + expf(-x));
                sRes[(s * 16 + t) * 17 + w] = fminf(ssp, dn) * sig;
            }
        }
    }
    __syncthreads();

    int pbase = blockIdx.x * 16;
    for (int i = tid; i < 4096; i += 512) {
        int st = i >> 4, pw = i & 15;
        outT[st * P + pbase + pw] = sRes[st * 17 + pw];
    }
}

// ---------------------------------------------------------------------------
extern "C" void kernel_launch(void* const* d_in, const int* in_sizes, int n_in,
                              void* d_out, int out_size) {
    const float* current_stock     = (const float*)d_in[0];
    const float* demand_forecast   = (const float*)d_in[1];
    const float* lead_times        = (const float*)d_in[2];
    const float* warehouse_stocks  = (const float*)d_in[3];
    const float* warehouse_demands = (const float*)d_in[4];
    const float* part_emb          = (const float*)d_in[5];
    const float* wh_emb            = (const float*)d_in[6];
    const float* W1r               = (const float*)d_in[7];
    const float* b1r               = (const float*)d_in[8];
    const float* W2r               = (const float*)d_in[9];
    const float* b2r               = (const float*)d_in[10];
    const float* W1t               = (const float*)d_in[11];
    const float* b1t               = (const float*)d_in[12];
    const float* W2t               = (const float*)d_in[13];
    const float* b2t               = (const float*)d_in[14];

    float* out_reorder  = (float*)d_out;              // [B, P]
    float* out_transfer = (float*)d_out + B * P;      // [W, W, P]

    k_pre<<<25, 256>>>(wh_emb, W1r, b1r, W1t, b1t);
    k_emb<<<P / 8, 256>>>(part_emb);
    k_reorder<<<2048, 256>>>(current_stock, demand_forecast, lead_times,
                             W1r, W2r, b2r, out_reorder);
    k_transfer<<<P / 16, 512>>>(warehouse_stocks, warehouse_demands,
                                W1t, W2t, b2t, out_transfer);
}

// round 3
// speedup vs baseline: 1.1372x; 1.1372x over previous
#include <cuda_runtime.h>
#include <math.h>

#define FULL 0xFFFFFFFFu
typedef unsigned long long ull;

constexpr int B  = 64;
constexpr int P  = 4096;
constexpr int W  = 16;
constexpr int D  = 128;
constexpr int Dw = 64;

// W1r is (D, D+4) row-major -> row stride 132
// W1t is (D, 2*Dw+2) row-major -> row stride 130

// Scratch
__device__ float g_WT[D * D];     // g_WT[k*D + d] = W1r[d,k]
__device__ float g_bias[D];       // b1r[d] + 0.95 * W1r[d,130]
__device__ float g_src[W * D];    // wh_emb @ W1t_src.T + b1t
__device__ float g_tgt[W * D];    // wh_emb @ W1t_tgt.T
__device__ float g_emb[P * D];    // emb_term with bias folded

// ---- f32x2 packed helpers (Blackwell dual-rate fp32) ----
__device__ __forceinline__ ull pk2(float a, float b) {
    ull r; asm("mov.b64 %0, {%1, %2};" : "=l"(r) : "f"(a), "f"(b)); return r;
}
__device__ __forceinline__ void upk2(ull d, float& a, float& b) {
    asm("mov.b64 {%0, %1}, %2;" : "=f"(a), "=f"(b) : "l"(d));
}
__device__ __forceinline__ ull fma2(ull a, ull b, ull c) {
    ull d; asm("fma.rn.f32x2 %0, %1, %2, %3;" : "=l"(d) : "l"(a), "l"(b), "l"(c)); return d;
}

// ---------------------------------------------------------------------------
// k_pre
// ---------------------------------------------------------------------------
__global__ void k_pre(const float* __restrict__ wh_emb,
                      const float* __restrict__ W1r,
                      const float* __restrict__ b1r,
                      const float* __restrict__ W1t,
                      const float* __restrict__ b1t) {
    int blk = blockIdx.x, tid = threadIdx.x;
    if (blk < 8) {
        #pragma unroll
        for (int j = 0; j < 8; j++) {
            int e = blk * 2048 + tid + j * 256;
            int d = e >> 7, k = e & 127;
            g_WT[k * D + d] = W1r[d * 132 + k];
        }
    } else if (blk < 24) {
        int out = (blk - 8) * 256 + tid;
        int arr = out >> 11;
        int rem = out & 2047;
        int s = rem >> 7, d = rem & 127;
        const float* wrow = wh_emb + s * Dw;
        const float* wcol = W1t + d * 130 + arr * Dw;
        float acc = (arr == 0) ? b1t[d] : 0.f;
        #pragma unroll 8
        for (int k = 0; k < Dw; k++) acc = fmaf(wrow[k], wcol[k], acc);
        if (arr == 0) g_src[s * D + d] = acc;
        else          g_tgt[s * D + d] = acc;
    } else {
        if (tid < D) g_bias[tid] = b1r[tid] + 0.95f * W1r[tid * 132 + 130];
    }
}

// ---------------------------------------------------------------------------
// k_emb: 4 p per warp (weight-load amortization). grid 256 x 128.
// ---------------------------------------------------------------------------
__global__ void k_emb(const float* __restrict__ part_emb) {
    int w = threadIdx.x >> 5, lane = threadIdx.x & 31;
    int p0 = (blockIdx.x * 4 + w) * 4;
    const float4* e0 = (const float4*)(part_emb + (p0 + 0) * D);
    const float4* e1 = (const float4*)(part_emb + (p0 + 1) * D);
    const float4* e2 = (const float4*)(part_emb + (p0 + 2) * D);
    const float4* e3 = (const float4*)(part_emb + (p0 + 3) * D);
    float4 bias = ((const float4*)g_bias)[lane];
    float4 a0 = bias, a1 = bias, a2 = bias, a3 = bias;
    #pragma unroll 4
    for (int k4 = 0; k4 < 32; k4++) {
        const float4* wt = (const float4*)(g_WT + k4 * 4 * D);
        float4 w0 = wt[lane];
        float4 w1 = wt[32 + lane];
        float4 w2 = wt[64 + lane];
        float4 w3 = wt[96 + lane];
        float4 ea = __ldg(&e0[k4]);
        float4 eb = __ldg(&e1[k4]);
        float4 ec = __ldg(&e2[k4]);
        float4 ed = __ldg(&e3[k4]);
        #define ACC(A, E) \
            A.x = fmaf(E.x, w0.x, fmaf(E.y, w1.x, fmaf(E.z, w2.x, fmaf(E.w, w3.x, A.x)))); \
            A.y = fmaf(E.x, w0.y, fmaf(E.y, w1.y, fmaf(E.z, w2.y, fmaf(E.w, w3.y, A.y)))); \
            A.z = fmaf(E.x, w0.z, fmaf(E.y, w1.z, fmaf(E.z, w2.z, fmaf(E.w, w3.z, A.z)))); \
            A.w = fmaf(E.x, w0.w, fmaf(E.y, w1.w, fmaf(E.z, w2.w, fmaf(E.w, w3.w, A.w))));
        ACC(a0, ea) ACC(a1, eb) ACC(a2, ec) ACC(a3, ed)
        #undef ACC
    }
    ((float4*)(g_emb + (p0 + 0) * D))[lane] = a0;
    ((float4*)(g_emb + (p0 + 1) * D))[lane] = a1;
    ((float4*)(g_emb + (p0 + 2) * D))[lane] = a2;
    ((float4*)(g_emb + (p0 + 3) * D))[lane] = a3;
}

// ---------------------------------------------------------------------------
// k_reorder: block = 8 warps; warp handles (b, 32 consecutive p), d-serial,
// emb tile in smem reused across 8 b. f32x2 packed fma. grid 1024 x 256.
// ---------------------------------------------------------------------------
__global__ void k_reorder(const float* __restrict__ cur_stock,
                          const float* __restrict__ demand,
                          const float* __restrict__ lead,
                          const float* __restrict__ W1r,
                          const float* __restrict__ W2r,
                          const float* __restrict__ b2r,
                          float* __restrict__ out) {
    __shared__ float sE[32 * 132];      // emb tile, padded row stride 132
    __shared__ float sC[4 * 128];       // c0, c1, c3, v
    int tid = threadIdx.x;
    int ptile = blockIdx.x & 127;
    int bgrp  = blockIdx.x >> 7;

    for (int i = tid; i < 32 * 128; i += 256) {
        int r = i >> 7, c = i & 127;
        sE[r * 132 + c] = g_emb[(ptile * 32 + r) * 128 + c];
    }
    if (tid < 128) {
        sC[tid]       = W1r[tid * 132 + 128];
        sC[128 + tid] = W1r[tid * 132 + 129];
        sC[256 + tid] = W1r[tid * 132 + 131];
        sC[384 + tid] = W2r[tid];
    }
    __syncthreads();

    int w = tid >> 5, lane = tid & 31;
    int b = bgrp * 8 + w;
    int p = ptile * 32 + lane;
    int item = b * P + p;
    float df = demand[item], lt = lead[item], cs = cur_stock[item];
    ull df2 = pk2(df, df), lt2 = pk2(lt, lt), cs2 = pk2(cs, cs);

    const ulonglong2* eRow = (const ulonglong2*)(sE + lane * 132);
    const ulonglong2* C0 = (const ulonglong2*)(sC);
    const ulonglong2* C1 = (const ulonglong2*)(sC + 128);
    const ulonglong2* C3 = (const ulonglong2*)(sC + 256);
    const float4*     V4 = (const float4*)(sC + 384);

    float s0 = 0.f, s1 = 0.f, s2 = 0.f, s3 = 0.f;
    #pragma unroll 4
    for (int j = 0; j < 32; j++) {
        ulonglong2 e2 = eRow[j];
        ulonglong2 c0 = C0[j];
        ulonglong2 c1 = C1[j];
        ulonglong2 c3 = C3[j];
        float4 v = V4[j];
        ull t0 = fma2(cs2, c3.x, fma2(lt2, c1.x, fma2(df2, c0.x, e2.x)));
        ull t1 = fma2(cs2, c3.y, fma2(lt2, c1.y, fma2(df2, c0.y, e2.y)));
        float h0, h1, h2, h3;
        upk2(t0, h0, h1);
        upk2(t1, h2, h3);
        s0 = fmaf(fmaxf(h0, 0.f), v.x, s0);
        s1 = fmaf(fmaxf(h1, 0.f), v.y, s1);
        s2 = fmaf(fmaxf(h2, 0.f), v.z, s2);
        s3 = fmaf(fmaxf(h3, 0.f), v.w, s3);
    }
    float x = (s0 + s1) + (s2 + s3) + b2r[0];
    // stable softplus with fast exp
    out[item] = fmaxf(x, 0.f) + log1pf(__expf(-fabsf(x)));
}

// ---------------------------------------------------------------------------
// k_transfer: 2 warps per p (split source list by parity) -> 2x occupancy.
// Uniform fast sigmoid. grid 512 x 512 (8 p per block).
// ---------------------------------------------------------------------------
__global__ void k_transfer(const float* __restrict__ wstk,
                           const float* __restrict__ wdem,
                           const float* __restrict__ W1t,
                           const float* __restrict__ W2t,
                           const float* __restrict__ b2t,
                           float* __restrict__ outT) {
    __shared__ float sSrc[W * D];
    __shared__ float sTgt[W * D];
    __shared__ float sWs[D], sWd[D], sV[D];
    __shared__ float sRes[256 * 9];     // [s*16+t][8 p + pad]
    int tid = threadIdx.x;
    for (int i = tid; i < W * D; i += 512) { sSrc[i] = g_src[i]; sTgt[i] = g_tgt[i]; }
    if (tid < D) {
        sWs[tid] = W1t[tid * 130 + 128];
        sWd[tid] = W1t[tid * 130 + 129];
        sV[tid]  = W2t[tid];
    }
    for (int i = tid; i < 256 * 9; i += 512) sRes[i] = 0.f;
    __syncthreads();

    int w = tid >> 5, lane = tid & 31;
    int pslot = w >> 1;                 // 0..7
    int q = w & 1;                      // source-parity this warp owns
    int pbase = blockIdx.x * 8;
    int p = pbase + pslot;

    float4 ws4 = ((float4*)sWs)[lane];
    float4 wd4 = ((float4*)sWd)[lane];
    float4 v4  = ((float4*)sV)[lane];

    float sv = 0.f;
    if (lane < W) sv = wstk[lane * P + p] - wdem[lane * P + p];
    unsigned pos = __ballot_sync(FULL, (lane < W) && (sv > 0.f));
    unsigned neg = __ballot_sync(FULL, (lane < W) && (sv < 0.f));

    float b2 = b2t[0];
    int cnt = 0;
    for (unsigned pm = pos; pm; pm &= pm - 1, cnt++) {
        if ((cnt & 1) != q) continue;
        int s = __ffs(pm) - 1;
        float ssp = __shfl_sync(FULL, sv, s);
        float4 sr = ((float4*)(sSrc + s * D))[lane];
        float4 base;
        base.x = fmaf(ssp, ws4.x, sr.x);
        base.y = fmaf(ssp, ws4.y, sr.y);
        base.z = fmaf(ssp, ws4.z, sr.z);
        base.w = fmaf(ssp, ws4.w, sr.w);
        for (unsigned nm = neg; nm; nm &= nm - 1) {
            int t = __ffs(nm) - 1;
            float dn = -__shfl_sync(FULL, sv, t);
            float4 tg = ((float4*)(sTgt + t * D))[lane];
            float4 h;
            h.x = fmaxf(base.x + fmaf(dn, wd4.x, tg.x), 0.f);
            h.y = fmaxf(base.y + fmaf(dn, wd4.y, tg.y), 0.f);
            h.z = fmaxf(base.z + fmaf(dn, wd4.z, tg.z), 0.f);
            h.w = fmaxf(base.w + fmaf(dn, wd4.w, tg.w), 0.f);
            float sc = fmaf(h.x, v4.x, fmaf(h.y, v4.y, fmaf(h.z, v4.z, h.w * v4.w)));
            sc += __shfl_xor_sync(FULL, sc, 16);
            sc += __shfl_xor_sync(FULL, sc, 8);
            sc += __shfl_xor_sync(FULL, sc, 4);
            sc += __shfl_xor_sync(FULL, sc, 2);
            sc += __shfl_xor_sync(FULL, sc, 1);
            // uniform across warp: fast sigmoid, no divergence
            float x = sc + b2;
            float sig = __fdividef(1.f, 1.f + __expf(-x));
            float qty = fminf(ssp, dn) * sig;
            if (lane == 0) sRes[(s * 16 + t) * 9 + pslot] = qty;
        }
    }
    __syncthreads();

    for (int i = tid; i < 2048; i += 512) {
        int st = i >> 3, pw = i & 7;
        outT[st * P + pbase + pw] = sRes[st * 9 + pw];
    }
}

// ---------------------------------------------------------------------------
extern "C" void kernel_launch(void* const* d_in, const int* in_sizes, int n_in,
                              void* d_out, int out_size) {
    const float* current_stock     = (const float*)d_in[0];
    const float* demand_forecast   = (const float*)d_in[1];
    const float* lead_times        = (const float*)d_in[2];
    const float* warehouse_stocks  = (const float*)d_in[3];
    const float* warehouse_demands = (const float*)d_in[4];
    const float* part_emb          = (const float*)d_in[5];
    const float* wh_emb            = (const float*)d_in[6];
    const float* W1r               = (const float*)d_in[7];
    const float* b1r               = (const float*)d_in[8];
    const float* W2r               = (const float*)d_in[9];
    const float* b2r               = (const float*)d_in[10];
    const float* W1t               = (const float*)d_in[11];
    const float* b1t               = (const float*)d_in[12];
    const float* W2t               = (const float*)d_in[13];
    const float* b2t               = (const float*)d_in[14];

    float* out_reorder  = (float*)d_out;              // [B, P]
    float* out_transfer = (float*)d_out + B * P;      // [W, W, P]

    k_pre<<<25, 256>>>(wh_emb, W1r, b1r, W1t, b1t);
    k_emb<<<256, 128>>>(part_emb);
    k_reorder<<<1024, 256>>>(current_stock, demand_forecast, lead_times,
                             W1r, W2r, b2r, out_reorder);
    k_transfer<<<512, 512>>>(warehouse_stocks, warehouse_demands,
                             W1t, W2t, b2t, out_transfer);
}

// round 5
// speedup vs baseline: 1.5736x; 1.3838x over previous
#include <cuda_runtime.h>
#include <math.h>

#define FULL 0xFFFFFFFFu

constexpr int B  = 64;
constexpr int P  = 4096;
constexpr int W  = 16;
constexpr int D  = 128;
constexpr int Dw = 64;

// W1r is (D, D+4) row-major -> row stride 132
// W1t is (D, 2*Dw+2) row-major -> row stride 130

__device__ float g_WT[D * D];     // g_WT[k*D + d] = W1r[d,k]
__device__ float g_bias[D];       // b1r[d] + 0.95 * W1r[d,130]
__device__ float g_src[W * D];    // wh_emb @ W1t_src.T + b1t
__device__ float g_tgt[W * D];    // wh_emb @ W1t_tgt.T
__device__ float g_emb[P * D];    // emb_term with bias folded

// ---------------------------------------------------------------------------
// 4-way batched warp reduction:
// input: s0..s3 (per-lane partials of 4 independent sums)
// output: every lane holds one total; lane group (bit4=lane&16, bit3=lane&8)
// maps to j = ((lane>>4)&1) | ((lane>>2)&2)  ->  totals of s_j.
// 6 shuffles for 4 reductions (vs 20 naive).
// ---------------------------------------------------------------------------
__device__ __forceinline__ float fold4(float s0, float s1, float s2, float s3) {
    bool hi16 = (threadIdx.x & 16) != 0;
    bool hi8  = (threadIdx.x & 8) != 0;
    float a   = hi16 ? s0 : s1;
    float v01 = (hi16 ? s1 : s0) + __shfl_xor_sync(FULL, a, 16);
    float b   = hi16 ? s2 : s3;
    float v23 = (hi16 ? s3 : s2) + __shfl_xor_sync(FULL, b, 16);
    float c   = hi8 ? v01 : v23;
    float vv  = (hi8 ? v23 : v01) + __shfl_xor_sync(FULL, c, 8);
    vv += __shfl_xor_sync(FULL, vv, 4);
    vv += __shfl_xor_sync(FULL, vv, 2);
    vv += __shfl_xor_sync(FULL, vv, 1);
    return vv;
}

// ---------------------------------------------------------------------------
// k_pre
// ---------------------------------------------------------------------------
__global__ void k_pre(const float* __restrict__ wh_emb,
                      const float* __restrict__ W1r,
                      const float* __restrict__ b1r,
                      const float* __restrict__ W1t,
                      const float* __restrict__ b1t) {
    int blk = blockIdx.x, tid = threadIdx.x;
    if (blk < 8) {
        #pragma unroll
        for (int j = 0; j < 8; j++) {
            int e = blk * 2048 + tid + j * 256;
            int d = e >> 7, k = e & 127;
            g_WT[k * D + d] = W1r[d * 132 + k];
        }
    } else if (blk < 24) {
        int out = (blk - 8) * 256 + tid;
        int arr = out >> 11;
        int rem = out & 2047;
        int s = rem >> 7, d = rem & 127;
        const float* wrow = wh_emb + s * Dw;
        const float* wcol = W1t + d * 130 + arr * Dw;
        float acc = (arr == 0) ? b1t[d] : 0.f;
        #pragma unroll 8
        for (int k = 0; k < Dw; k++) acc = fmaf(wrow[k], wcol[k], acc);
        if (arr == 0) g_src[s * D + d] = acc;
        else          g_tgt[s * D + d] = acc;
    } else {
        if (tid < D) g_bias[tid] = b1r[tid] + 0.95f * W1r[tid * 132 + 130];
    }
}

// ---------------------------------------------------------------------------
// k_fused: blocks [0,512) transfer (8 p each), blocks [512,576) emb (64 p each)
// ---------------------------------------------------------------------------
__global__ void k_fused(const float* __restrict__ part_emb,
                        const float* __restrict__ wstk,
                        const float* __restrict__ wdem,
                        const float* __restrict__ W1t,
                        const float* __restrict__ W2t,
                        const float* __restrict__ b2t,
                        float* __restrict__ outT) {
    __shared__ float sSrc[W * D];
    __shared__ float sTgt[W * D];
    __shared__ float sWs[D], sWd[D], sV[D];
    __shared__ float sRes[256 * 9];     // raw scores [s*16+t][8 p + pad]
    __shared__ float sSv[8 * 17];       // surplus per p
    __shared__ int   sPl[8 * 17];       // compacted source list per p
    __shared__ int   sTl[8 * 17];       // compacted target list per p

    int tid = threadIdx.x;
    int bid = blockIdx.x;

    if (bid >= 512) {
        // ---------------- emb role: 16 warps x 4 p ----------------
        int w = tid >> 5, lane = tid & 31;
        int p0 = ((bid - 512) * 16 + w) * 4;
        const float4* e0 = (const float4*)(part_emb + (p0 + 0) * D);
        const float4* e1 = (const float4*)(part_emb + (p0 + 1) * D);
        const float4* e2 = (const float4*)(part_emb + (p0 + 2) * D);
        const float4* e3 = (const float4*)(part_emb + (p0 + 3) * D);
        float4 bias = ((const float4*)g_bias)[lane];
        float4 a0 = bias, a1 = bias, a2 = bias, a3 = bias;
        #pragma unroll 4
        for (int k4 = 0; k4 < 32; k4++) {
            const float4* wt = (const float4*)(g_WT + k4 * 4 * D);
            float4 w0 = wt[lane];
            float4 w1 = wt[32 + lane];
            float4 w2 = wt[64 + lane];
            float4 w3 = wt[96 + lane];
            float4 ea = __ldg(&e0[k4]);
            float4 eb = __ldg(&e1[k4]);
            float4 ec = __ldg(&e2[k4]);
            float4 ed = __ldg(&e3[k4]);
            #define ACC(A, E) \
                A.x = fmaf(E.x, w0.x, fmaf(E.y, w1.x, fmaf(E.z, w2.x, fmaf(E.w, w3.x, A.x)))); \
                A.y = fmaf(E.x, w0.y, fmaf(E.y, w1.y, fmaf(E.z, w2.y, fmaf(E.w, w3.y, A.y)))); \
                A.z = fmaf(E.x, w0.z, fmaf(E.y, w1.z, fmaf(E.z, w2.z, fmaf(E.w, w3.z, A.z)))); \
                A.w = fmaf(E.x, w0.w, fmaf(E.y, w1.w, fmaf(E.z, w2.w, fmaf(E.w, w3.w, A.w))));
            ACC(a0, ea) ACC(a1, eb) ACC(a2, ec) ACC(a3, ed)
            #undef ACC
        }
        ((float4*)(g_emb + (p0 + 0) * D))[lane] = a0;
        ((float4*)(g_emb + (p0 + 1) * D))[lane] = a1;
        ((float4*)(g_emb + (p0 + 2) * D))[lane] = a2;
        ((float4*)(g_emb + (p0 + 3) * D))[lane] = a3;
        return;
    }

    // ---------------- transfer role: 16 warps = 8 p x 2 parity ----------------
    for (int i = tid; i < W * D; i += 512) { sSrc[i] = g_src[i]; sTgt[i] = g_tgt[i]; }
    if (tid < D) {
        sWs[tid] = W1t[tid * 130 + 128];
        sWd[tid] = W1t[tid * 130 + 129];
        sV[tid]  = W2t[tid];
    }

    int w = tid >> 5, lane = tid & 31;
    int pslot = w >> 1;                 // 0..7
    int q = w & 1;                      // source-parity this warp owns
    int pbase = bid * 8;
    int p = pbase + pslot;

    float sv = 0.f;
    if (lane < W) sv = wstk[lane * P + p] - wdem[lane * P + p];
    unsigned pos = __ballot_sync(FULL, (lane < W) && (sv > 0.f));
    unsigned neg = __ballot_sync(FULL, (lane < W) && (sv < 0.f));
    int npos = __popc(pos);
    int nneg = __popc(neg);

    if (q == 0 && lane < W) {
        sSv[pslot * 17 + lane] = sv;
        unsigned bit = 1u << lane;
        if (pos & bit) sPl[pslot * 17 + __popc(pos & (bit - 1))] = lane;
        if (neg & bit) sTl[pslot * 17 + __popc(neg & (bit - 1))] = lane;
    }
    __syncthreads();

    float4 ws4 = ((float4*)sWs)[lane];
    float4 wd4 = ((float4*)sWd)[lane];
    float4 v4  = ((float4*)sV)[lane];

    const float* svRow = sSv + pslot * 17;
    const int*   tl    = sTl + pslot * 17;
    int jm = ((lane >> 4) & 1) | ((lane >> 2) & 2);   // which of the 4 batched sums this lane group holds

    for (int si = q; si < npos; si += 2) {
        int s = sPl[pslot * 17 + si];
        float ssp = svRow[s];
        float4 sr = ((float4*)(sSrc + s * D))[lane];
        float4 base;
        base.x = fmaf(ssp, ws4.x, sr.x);
        base.y = fmaf(ssp, ws4.y, sr.y);
        base.z = fmaf(ssp, ws4.z, sr.z);
        base.w = fmaf(ssp, ws4.w, sr.w);
        for (int ti = 0; ti < nneg; ti += 4) {
            float sA[4];
            int t0 = 0, t1 = 0, t2 = 0, t3 = 0;
            #pragma unroll
            for (int j = 0; j < 4; j++) {
                int idx = ti + j; if (idx > nneg - 1) idx = nneg - 1;
                int t = tl[idx];
                if (j == 0) t0 = t; else if (j == 1) t1 = t; else if (j == 2) t2 = t; else t3 = t;
                float dn = -svRow[t];
                float4 tg = ((float4*)(sTgt + t * D))[lane];
                float4 h;
                h.x = fmaxf(base.x + fmaf(dn, wd4.x, tg.x), 0.f);
                h.y = fmaxf(base.y + fmaf(dn, wd4.y, tg.y), 0.f);
                h.z = fmaxf(base.z + fmaf(dn, wd4.z, tg.z), 0.f);
                h.w = fmaxf(base.w + fmaf(dn, wd4.w, tg.w), 0.f);
                sA[j] = fmaf(h.x, v4.x, fmaf(h.y, v4.y, fmaf(h.z, v4.z, h.w * v4.w)));
            }
            float tot = fold4(sA[0], sA[1], sA[2], sA[3]);
            int tm = (lane & 16) ? ((lane & 8) ? t3 : t1)
                                 : ((lane & 8) ? t2 : t0);
            if (((lane & 7) == 0) && (ti + jm < nneg))
                sRes[(s * 16 + tm) * 9 + pslot] = tot;
        }
    }
    __syncthreads();

    // epilogue: mask + sigmoid + min, fully parallel
    float b2 = b2t[0];
    for (int i = tid; i < 2048; i += 512) {
        int st = i >> 3, pw = i & 7;
        int s = st >> 4, t = st & 15;
        float svs = sSv[pw * 17 + s];
        float svt = sSv[pw * 17 + t];
        float val = 0.f;
        if (svs > 0.f && svt < 0.f) {
            float x = sRes[st * 9 + pw] + b2;
            val = fminf(svs, -svt) * __fdividef(1.f, 1.f + __expf(-x));
        }
        outT[st * P + pbase + pw] = val;
    }
}

// ---------------------------------------------------------------------------
// k_reorder: warp per p, weights + e in registers, 4-b batched reduction,
// softplus in parallel epilogue. grid 512 x 256.
// ---------------------------------------------------------------------------
__global__ void k_reorder(const float* __restrict__ cur_stock,
                          const float* __restrict__ demand,
                          const float* __restrict__ lead,
                          const float* __restrict__ W1r,
                          const float* __restrict__ W2r,
                          const float* __restrict__ b2r,
                          float* __restrict__ out) {
    __shared__ float sC[4 * 128];
    __shared__ float sX[8][65];         // raw scores [p-slot][64 b + pad]
    int tid = threadIdx.x;
    if (tid < 128) {
        sC[tid]       = W1r[tid * 132 + 128];
        sC[128 + tid] = W1r[tid * 132 + 129];
        sC[256 + tid] = W1r[tid * 132 + 131];
        sC[384 + tid] = W2r[tid];
    }
    __syncthreads();

    int w = tid >> 5, lane = tid & 31;
    float4 c0 = ((float4*)sC)[lane];
    float4 c1 = ((float4*)(sC + 128))[lane];
    float4 c3 = ((float4*)(sC + 256))[lane];
    float4 v  = ((float4*)(sC + 384))[lane];

    int pbase = blockIdx.x * 8;
    int p = pbase + w;
    float4 e = ((const float4*)(g_emb + p * D))[lane];
    int jm = ((lane >> 4) & 1) | ((lane >> 2) & 2);

    #pragma unroll 2
    for (int bq = 0; bq < B; bq += 4) {
        float sA[4];
        #pragma unroll
        for (int j = 0; j < 4; j++) {
            int item = (bq + j) * P + p;
            float df = __ldg(&demand[item]);
            float lt = __ldg(&lead[item]);
            float cs = __ldg(&cur_stock[item]);
            float4 h;
            h.x = fmaxf(fmaf(cs, c3.x, fmaf(lt, c1.x, fmaf(df, c0.x, e.x))), 0.f);
            h.y = fmaxf(fmaf(cs, c3.y, fmaf(lt, c1.y, fmaf(df, c0.y, e.y))), 0.f);
            h.z = fmaxf(fmaf(cs, c3.z, fmaf(lt, c1.z, fmaf(df, c0.z, e.z))), 0.f);
            h.w = fmaxf(fmaf(cs, c3.w, fmaf(lt, c1.w, fmaf(df, c0.w, e.w))), 0.f);
            sA[j] = fmaf(h.x, v.x, fmaf(h.y, v.y, fmaf(h.z, v.z, h.w * v.w)));
        }
        float tot = fold4(sA[0], sA[1], sA[2], sA[3]);
        if ((lane & 7) == 0) sX[w][bq + jm] = tot;
    }
    __syncthreads();

    float bb = b2r[0];
    for (int i = tid; i < 512; i += 256) {
        int b = i >> 3, pw = i & 7;
        float x = sX[pw][b] + bb;
        out[b * P + pbase + pw] = fmaxf(x, 0.f) + log1pf(__expf(-fabsf(x)));
    }
}

// ---------------------------------------------------------------------------
extern "C" void kernel_launch(void* const* d_in, const int* in_sizes, int n_in,
                              void* d_out, int out_size) {
    const float* current_stock     = (const float*)d_in[0];
    const float* demand_forecast   = (const float*)d_in[1];
    const float* lead_times        = (const float*)d_in[2];
    const float* warehouse_stocks  = (const float*)d_in[3];
    const float* warehouse_demands = (const float*)d_in[4];
    const float* part_emb          = (const float*)d_in[5];
    const float* wh_emb            = (const float*)d_in[6];
    const float* W1r               = (const float*)d_in[7];
    const float* b1r               = (const float*)d_in[8];
    const float* W2r               = (const float*)d_in[9];
    const float* b2r               = (const float*)d_in[10];
    const float* W1t               = (const float*)d_in[11];
    const float* b1t               = (const float*)d_in[12];
    const float* W2t               = (const float*)d_in[13];
    const float* b2t               = (const float*)d_in[14];

    float* out_reorder  = (float*)d_out;              // [B, P]
    float* out_transfer = (float*)d_out + B * P;      // [W, W, P]

    k_pre<<<25, 256>>>(wh_emb, W1r, b1r, W1t, b1t);
    k_fused<<<576, 512>>>(part_emb, warehouse_stocks, warehouse_demands,
                          W1t, W2t, b2t, out_transfer);
    k_reorder<<<512, 256>>>(current_stock, demand_forecast, lead_times,
                            W1r, W2r, b2r, out_reorder);
}

// round 6
// speedup vs baseline: 1.7057x; 1.0840x over previous
#include <cuda_runtime.h>
#include <math.h>

#define FULL 0xFFFFFFFFu

constexpr int B  = 64;
constexpr int P  = 4096;
constexpr int W  = 16;
constexpr int D  = 128;
constexpr int Dw = 64;

// W1r: (D, D+4) row-major, stride 132.  W1t: (D, 2*Dw+2) row-major, stride 130.

__device__ float g_src[W * D];    // wh_emb @ W1t_src.T + b1t
__device__ float g_tgt[W * D];    // wh_emb @ W1t_tgt.T
__device__ float g_emb[P * D];    // part_emb @ W1r_e.T + b1r + 0.95*W1r[:,130]

// ---------------------------------------------------------------------------
// 4-way batched warp reduction (6 shuffles for 4 sums).
// lane group j = ((lane>>4)&1) | ((lane>>2)&2) holds total of s_j.
// ---------------------------------------------------------------------------
__device__ __forceinline__ float fold4(float s0, float s1, float s2, float s3) {
    bool hi16 = (threadIdx.x & 16) != 0;
    bool hi8  = (threadIdx.x & 8) != 0;
    float a   = hi16 ? s0 : s1;
    float v01 = (hi16 ? s1 : s0) + __shfl_xor_sync(FULL, a, 16);
    float b   = hi16 ? s2 : s3;
    float v23 = (hi16 ? s3 : s2) + __shfl_xor_sync(FULL, b, 16);
    float c   = hi8 ? v01 : v23;
    float vv  = (hi8 ? v23 : v01) + __shfl_xor_sync(FULL, c, 8);
    vv += __shfl_xor_sync(FULL, vv, 4);
    vv += __shfl_xor_sync(FULL, vv, 2);
    vv += __shfl_xor_sync(FULL, vv, 1);
    return vv;
}

// ---------------------------------------------------------------------------
// k_head (launch 1, 144 blocks x 256 thr, dyn smem 68096B):
//   blocks [0,128): emb — transpose W1r into local smem, compute g_emb (32 p each)
//   blocks [128,144): src/tgt mini-GEMMs
// ---------------------------------------------------------------------------
__global__ void k_head(const float* __restrict__ part_emb,
                       const float* __restrict__ wh_emb,
                       const float* __restrict__ W1r,
                       const float* __restrict__ b1r,
                       const float* __restrict__ W1t,
                       const float* __restrict__ b1t) {
    extern __shared__ float dsm[];          // sWT[128*132] + sBias[128]
    int bid = blockIdx.x, tid = threadIdx.x;

    if (bid >= 128) {
        // ---- src/tgt role: one dot per thread ----
        int idx = (bid - 128) * 256 + tid;  // 0..4095
        int arr = idx >> 11;                // 0 = src, 1 = tgt
        int rem = idx & 2047;
        int s = rem >> 7, d = rem & 127;
        const float* wrow = wh_emb + s * Dw;
        const float* wcol = W1t + d * 130 + arr * Dw;
        float acc = (arr == 0) ? b1t[d] : 0.f;
        #pragma unroll 8
        for (int k = 0; k < Dw; k++) acc = fmaf(wrow[k], wcol[k], acc);
        if (arr == 0) g_src[s * D + d] = acc;
        else          g_tgt[s * D + d] = acc;
        return;
    }

    // ---- emb role ----
    float* sWT   = dsm;                     // [k*132 + d]
    float* sBias = dsm + 128 * 132;
    for (int i = tid; i < 128 * 128; i += 256) {
        int d = i >> 7, k = i & 127;
        sWT[k * 132 + d] = W1r[d * 132 + k];
    }
    if (tid < 128) sBias[tid] = b1r[tid] + 0.95f * W1r[tid * 132 + 130];
    __syncthreads();

    int w = tid >> 5, lane = tid & 31;
    int p0 = bid * 32 + w * 4;
    const float4* e0 = (const float4*)(part_emb + (p0 + 0) * D);
    const float4* e1 = (const float4*)(part_emb + (p0 + 1) * D);
    const float4* e2 = (const float4*)(part_emb + (p0 + 2) * D);
    const float4* e3 = (const float4*)(part_emb + (p0 + 3) * D);
    float4 bias = ((const float4*)sBias)[lane];
    float4 a0 = bias, a1 = bias, a2 = bias, a3 = bias;
    #pragma unroll 4
    for (int k4 = 0; k4 < 32; k4++) {
        const float* wt = sWT + k4 * 4 * 132;
        float4 w0 = ((const float4*)(wt))[lane];
        float4 w1 = ((const float4*)(wt + 132))[lane];
        float4 w2 = ((const float4*)(wt + 264))[lane];
        float4 w3 = ((const float4*)(wt + 396))[lane];
        float4 ea = __ldg(&e0[k4]);
        float4 eb = __ldg(&e1[k4]);
        float4 ec = __ldg(&e2[k4]);
        float4 ed = __ldg(&e3[k4]);
        #define ACC(A, E) \
            A.x = fmaf(E.x, w0.x, fmaf(E.y, w1.x, fmaf(E.z, w2.x, fmaf(E.w, w3.x, A.x)))); \
            A.y = fmaf(E.x, w0.y, fmaf(E.y, w1.y, fmaf(E.z, w2.y, fmaf(E.w, w3.y, A.y)))); \
            A.z = fmaf(E.x, w0.z, fmaf(E.y, w1.z, fmaf(E.z, w2.z, fmaf(E.w, w3.z, A.z)))); \
            A.w = fmaf(E.x, w0.w, fmaf(E.y, w1.w, fmaf(E.z, w2.w, fmaf(E.w, w3.w, A.w))));
        ACC(a0, ea) ACC(a1, eb) ACC(a2, ec) ACC(a3, ed)
        #undef ACC
    }
    ((float4*)(g_emb + (p0 + 0) * D))[lane] = a0;
    ((float4*)(g_emb + (p0 + 1) * D))[lane] = a1;
    ((float4*)(g_emb + (p0 + 2) * D))[lane] = a2;
    ((float4*)(g_emb + (p0 + 3) * D))[lane] = a3;
}

// ---------------------------------------------------------------------------
// k_main (launch 2, 768 blocks x 512 thr):
//   blocks [0,512): transfer, 8 p each
//   blocks [512,768): reorder, 16 p each (warp per p)
// ---------------------------------------------------------------------------
__global__ void k_main(const float* __restrict__ cur_stock,
                       const float* __restrict__ demand,
                       const float* __restrict__ lead,
                       const float* __restrict__ wstk,
                       const float* __restrict__ wdem,
                       const float* __restrict__ W1r,
                       const float* __restrict__ W2r,
                       const float* __restrict__ b2r,
                       const float* __restrict__ W1t,
                       const float* __restrict__ W2t,
                       const float* __restrict__ b2t,
                       float* __restrict__ outR,
                       float* __restrict__ outT) {
    __shared__ union {
        struct {
            float sSrc[W * D];
            float sTgt[W * D];
            float sWs[D], sWd[D], sV[D];
            float sRes[256 * 9];
            float sSv[8 * 17];
            int   sPl[8 * 17];
            int   sTl[8 * 17];
        } t;
        struct {
            float sC[4 * 128];
            float sX[16][65];
        } r;
    } sm;

    int tid = threadIdx.x;
    int bid = blockIdx.x;
    int w = tid >> 5, lane = tid & 31;

    if (bid >= 512) {
        // ================= reorder role =================
        if (tid < 128) {
            sm.r.sC[tid]       = W1r[tid * 132 + 128];
            sm.r.sC[128 + tid] = W1r[tid * 132 + 129];
            sm.r.sC[256 + tid] = W1r[tid * 132 + 131];
            sm.r.sC[384 + tid] = W2r[tid];
        }
        __syncthreads();

        float4 c0 = ((float4*)sm.r.sC)[lane];
        float4 c1 = ((float4*)(sm.r.sC + 128))[lane];
        float4 c3 = ((float4*)(sm.r.sC + 256))[lane];
        float4 v  = ((float4*)(sm.r.sC + 384))[lane];

        int pbase = (bid - 512) * 16;
        int p = pbase + w;
        float4 e = ((const float4*)(g_emb + p * D))[lane];
        int jm = ((lane >> 4) & 1) | ((lane >> 2) & 2);

        #pragma unroll 2
        for (int bq = 0; bq < B; bq += 4) {
            float sA[4];
            #pragma unroll
            for (int j = 0; j < 4; j++) {
                int item = (bq + j) * P + p;
                float df = __ldg(&demand[item]);
                float lt = __ldg(&lead[item]);
                float cs = __ldg(&cur_stock[item]);
                float4 h;
                h.x = fmaxf(fmaf(cs, c3.x, fmaf(lt, c1.x, fmaf(df, c0.x, e.x))), 0.f);
                h.y = fmaxf(fmaf(cs, c3.y, fmaf(lt, c1.y, fmaf(df, c0.y, e.y))), 0.f);
                h.z = fmaxf(fmaf(cs, c3.z, fmaf(lt, c1.z, fmaf(df, c0.z, e.z))), 0.f);
                h.w = fmaxf(fmaf(cs, c3.w, fmaf(lt, c1.w, fmaf(df, c0.w, e.w))), 0.f);
                sA[j] = fmaf(h.x, v.x, fmaf(h.y, v.y, fmaf(h.z, v.z, h.w * v.w)));
            }
            float tot = fold4(sA[0], sA[1], sA[2], sA[3]);
            if ((lane & 7) == 0) sm.r.sX[w][bq + jm] = tot;
        }
        __syncthreads();

        float bb = b2r[0];
        for (int i = tid; i < 1024; i += 512) {
            int b = i >> 4, pw = i & 15;
            float x = sm.r.sX[pw][b] + bb;
            outR[b * P + pbase + pw] = fmaxf(x, 0.f) + log1pf(__expf(-fabsf(x)));
        }
        return;
    }

    // ================= transfer role =================
    for (int i = tid; i < W * D; i += 512) { sm.t.sSrc[i] = g_src[i]; sm.t.sTgt[i] = g_tgt[i]; }
    if (tid < D) {
        sm.t.sWs[tid] = W1t[tid * 130 + 128];
        sm.t.sWd[tid] = W1t[tid * 130 + 129];
        sm.t.sV[tid]  = W2t[tid];
    }

    int pslot = w >> 1;
    int q = w & 1;
    int pbase = bid * 8;
    int p = pbase + pslot;

    float sv = 0.f;
    if (lane < W) sv = wstk[lane * P + p] - wdem[lane * P + p];
    unsigned pos = __ballot_sync(FULL, (lane < W) && (sv > 0.f));
    unsigned neg = __ballot_sync(FULL, (lane < W) && (sv < 0.f));
    int npos = __popc(pos);
    int nneg = __popc(neg);

    if (q == 0 && lane < W) {
        sm.t.sSv[pslot * 17 + lane] = sv;
        unsigned bit = 1u << lane;
        if (pos & bit) sm.t.sPl[pslot * 17 + __popc(pos & (bit - 1))] = lane;
        if (neg & bit) sm.t.sTl[pslot * 17 + __popc(neg & (bit - 1))] = lane;
    }
    __syncthreads();

    float4 ws4 = ((float4*)sm.t.sWs)[lane];
    float4 wd4 = ((float4*)sm.t.sWd)[lane];
    float4 v4  = ((float4*)sm.t.sV)[lane];

    const float* svRow = sm.t.sSv + pslot * 17;
    const int*   tl    = sm.t.sTl + pslot * 17;
    int jm = ((lane >> 4) & 1) | ((lane >> 2) & 2);

    for (int si = q; si < npos; si += 2) {
        int s = sm.t.sPl[pslot * 17 + si];
        float ssp = svRow[s];
        float4 sr = ((float4*)(sm.t.sSrc + s * D))[lane];
        float4 base;
        base.x = fmaf(ssp, ws4.x, sr.x);
        base.y = fmaf(ssp, ws4.y, sr.y);
        base.z = fmaf(ssp, ws4.z, sr.z);
        base.w = fmaf(ssp, ws4.w, sr.w);
        for (int ti = 0; ti < nneg; ti += 4) {
            float sA[4];
            int t0 = 0, t1 = 0, t2 = 0, t3 = 0;
            #pragma unroll
            for (int j = 0; j < 4; j++) {
                int idx = ti + j; if (idx > nneg - 1) idx = nneg - 1;
                int t = tl[idx];
                if (j == 0) t0 = t; else if (j == 1) t1 = t; else if (j == 2) t2 = t; else t3 = t;
                float dn = -svRow[t];
                float4 tg = ((float4*)(sm.t.sTgt + t * D))[lane];
                float4 h;
                h.x = fmaxf(base.x + fmaf(dn, wd4.x, tg.x), 0.f);
                h.y = fmaxf(base.y + fmaf(dn, wd4.y, tg.y), 0.f);
                h.z = fmaxf(base.z + fmaf(dn, wd4.z, tg.z), 0.f);
                h.w = fmaxf(base.w + fmaf(dn, wd4.w, tg.w), 0.f);
                sA[j] = fmaf(h.x, v4.x, fmaf(h.y, v4.y, fmaf(h.z, v4.z, h.w * v4.w)));
            }
            float tot = fold4(sA[0], sA[1], sA[2], sA[3]);
            int tm = (lane & 16) ? ((lane & 8) ? t3 : t1)
                                 : ((lane & 8) ? t2 : t0);
            if (((lane & 7) == 0) && (ti + jm < nneg))
                sm.t.sRes[(s * 16 + tm) * 9 + pslot] = tot;
        }
    }
    __syncthreads();

    float b2 = b2t[0];
    for (int i = tid; i < 2048; i += 512) {
        int st = i >> 3, pw = i & 7;
        int s = st >> 4, t = st & 15;
        float svs = sm.t.sSv[pw * 17 + s];
        float svt = sm.t.sSv[pw * 17 + t];
        float val = 0.f;
        if (svs > 0.f && svt < 0.f) {
            float x = sm.t.sRes[st * 9 + pw] + b2;
            val = fminf(svs, -svt) * __fdividef(1.f, 1.f + __expf(-x));
        }
        outT[st * P + pbase + pw] = val;
    }
}

// ---------------------------------------------------------------------------
extern "C" void kernel_launch(void* const* d_in, const int* in_sizes, int n_in,
                              void* d_out, int out_size) {
    const float* current_stock     = (const float*)d_in[0];
    const float* demand_forecast   = (const float*)d_in[1];
    const float* lead_times        = (const float*)d_in[2];
    const float* warehouse_stocks  = (const float*)d_in[3];
    const float* warehouse_demands = (const float*)d_in[4];
    const float* part_emb          = (const float*)d_in[5];
    const float* wh_emb            = (const float*)d_in[6];
    const float* W1r               = (const float*)d_in[7];
    const float* b1r               = (const float*)d_in[8];
    const float* W2r               = (const float*)d_in[9];
    const float* b2r               = (const float*)d_in[10];
    const float* W1t               = (const float*)d_in[11];
    const float* b1t               = (const float*)d_in[12];
    const float* W2t               = (const float*)d_in[13];
    const float* b2t               = (const float*)d_in[14];

    float* out_reorder  = (float*)d_out;              // [B, P]
    float* out_transfer = (float*)d_out + B * P;      // [W, W, P]

    const int dyn = (128 * 132 + 128) * sizeof(float);   // 68096 B
    static bool attr_set = false;
    if (!attr_set) {
        cudaFuncSetAttribute(k_head, cudaFuncAttributeMaxDynamicSharedMemorySize, dyn);
        attr_set = true;
    }

    k_head<<<144, 256, dyn>>>(part_emb, wh_emb, W1r, b1r, W1t, b1t);
    k_main<<<768, 512>>>(current_stock, demand_forecast, lead_times,
                         warehouse_stocks, warehouse_demands,
                         W1r, W2r, b2r, W1t, W2t, b2t,
                         out_reorder, out_transfer);
}